// round 8
// baseline (speedup 1.0000x reference)
#include <cuda_runtime.h>
#include <cstdint>

// Bond-percolation flood fill from a seed, 8192x8192 periodic lattice.
// Serialization PINNED by the round-7 memory dump:
//   in[0] links : int32 (2,8192,8192), values {0,1}  (512 MB)
//   in[1] seed  : int32 (2,)                          (8 bytes)
//   out         : float32 (8192,8192)  -> cluster cells must be 1.0f
//     (rounds 1-5 all wrote small-int bit patterns = f32 denormals ~= 0,
//      which is why rel_err was always exactly 1.0)
// p = 0.45 < pc = 0.5 (2D bond) -> the seed cluster is small. Plan:
//   1) cudaMemsetAsync(out, 0, 256 MB)  -- DRAM-write-bound floor (~32 us)
//   2) single-block level-synchronous BFS over int32 links, marking cells
//      with 0x3F800000 via atomicOr (mark + dedup in one op, no extra
//      visited state to reset -> graph-replayable and deterministic).
//
// Adjacency (verified against the reference's roll semantics):
//   bond links[0][a][b] connects (a,b) <-> (a+1 mod N, b)
//   bond links[1][a][b] connects (a,b) <-> (a, b+1 mod N)

#define GRID_N 8192
#define LOG2_N 13
#define NCELLS (GRID_N * GRID_N)
#define QCAP   (1 << 22)          // 16 MB static queue; >> subcritical cluster
#define ONE_F  0x3F800000u        // 1.0f

__device__ int d_queue[QCAP];

__global__ void __launch_bounds__(256, 1)
bfs_kernel(const unsigned int* __restrict__ links,
           const int* __restrict__ seed,
           unsigned int* __restrict__ out)
{
    const unsigned int* __restrict__ L0 = links;            // +axis0 bonds
    const unsigned int* __restrict__ L1 = links + NCELLS;   // +axis1 bonds
    const int tid = threadIdx.x;

    __shared__ int s_start, s_end, s_next;

    if (tid == 0) {
        const int a = seed[0] & (GRID_N - 1);
        const int b = seed[1] & (GRID_N - 1);
        const int idx = (a << LOG2_N) | b;
        atomicOr(&out[idx], ONE_F);
        d_queue[0] = idx;
        s_start = 0; s_end = 1; s_next = 1;
    }
    __syncthreads();

    while (true) {
        const int start = s_start;
        const int end   = s_end;
        if (start >= end) break;

        for (int i = start + tid; i < end; i += 256) {
            const int idx = d_queue[i];
            const int a = idx >> LOG2_N;
            const int b = idx & (GRID_N - 1);

            // periodic 4-neighborhood
            const int nA = (((a + 1) & (GRID_N - 1)) << LOG2_N) | b;  // +a
            const int mA = (((a - 1) & (GRID_N - 1)) << LOG2_N) | b;  // -a
            const int nB = (a << LOG2_N) | ((b + 1) & (GRID_N - 1));  // +b
            const int mB = (a << LOG2_N) | ((b - 1) & (GRID_N - 1));  // -b

            const bool o0 = L0[idx] != 0u;   // bond (a,b)<->(a+1,b)
            const bool o1 = L0[mA]  != 0u;   // bond (a-1,b)<->(a,b)
            const bool o2 = L1[idx] != 0u;   // bond (a,b)<->(a,b+1)
            const bool o3 = L1[mB]  != 0u;   // bond (a,b-1)<->(a,b)

            const int  nbr[4] = { nA, mA, nB, mB };
            const bool op [4] = { o0, o1, o2, o3 };

            #pragma unroll
            for (int d = 0; d < 4; d++) {
                if (!op[d]) continue;
                const int m = nbr[d];
                // atomicOr with 1.0f bits: old==0 iff newly marked
                if ((atomicOr(&out[m], ONE_F) & ONE_F) == 0u) {
                    const int p = atomicAdd(&s_next, 1);
                    if (p < QCAP) d_queue[p] = m;   // clamp: never fault
                }
            }
        }
        __syncthreads();
        if (tid == 0) {
            s_start = s_end;
            s_end   = (s_next < QCAP) ? s_next : QCAP;
        }
        __syncthreads();
    }
}

extern "C" void kernel_launch(void* const* d_in, const int* in_sizes, int n_in,
                              void* d_out, int out_size)
{
    const unsigned int* links = (const unsigned int*)d_in[0];
    const int*          seed  = (const int*)d_in[1];
    unsigned int*       out   = (unsigned int*)d_out;
    (void)in_sizes; (void)n_in;

    // Output is float32: zero 8192^2 * 4 = 256 MB (DRAM-write-bound).
    cudaMemsetAsync(out, 0, (size_t)out_size * sizeof(float));

    // Small latency-bound BFS marks the seed cluster with 1.0f.
    bfs_kernel<<<1, 256>>>(links, seed, out);
}